// round 12
// baseline (speedup 1.0000x reference)
#include <cuda_runtime.h>
#include <cstdint>
#include <math.h>

#define S_LEN 4096
#define DIM 1024
#define NH 16
#define HD 64
#define HALF_HD 32

// ---------------------------------------------------------------------------
// Scratch (allocation-free)
// ---------------------------------------------------------------------------
__device__ float g_q[S_LEN * DIM];
__device__ float g_k[S_LEN * DIM];
__device__ float g_v[S_LEN * DIM];
__device__ float g_o[S_LEN * DIM];
__device__ float g_xr[S_LEN * DIM];
__device__ float g_wr[4 * DIM * DIM];
__device__ float g_cos[S_LEN * HALF_HD];
__device__ float g_sin[S_LEN * HALF_HD];

// ---------------------------------------------------------------------------
// Helpers
// ---------------------------------------------------------------------------
__device__ __forceinline__ uint32_t smem_u32(const void* p) {
    uint32_t a;
    asm("{ .reg .u64 t; cvta.to.shared.u64 t, %1; cvt.u32.u64 %0, t; }"
        : "=r"(a) : "l"(p));
    return a;
}

#define CP16(dst, src) \
    asm volatile("cp.async.cg.shared.global [%0], [%1], 16;" :: "r"(dst), "l"(src))
#define CP_COMMIT() asm volatile("cp.async.commit_group;" ::: "memory")
#define CP_WAIT(n)  asm volatile("cp.async.wait_group %0;" :: "n"(n) : "memory")

__device__ __forceinline__ void mma_tf32(float* c, const uint32_t* a, const uint32_t* b)
{
    asm volatile(
        "mma.sync.aligned.m16n8k8.row.col.f32.tf32.tf32.f32 "
        "{%0,%1,%2,%3}, {%4,%5,%6,%7}, {%8,%9}, {%0,%1,%2,%3};"
        : "+f"(c[0]), "+f"(c[1]), "+f"(c[2]), "+f"(c[3])
        : "r"(a[0]), "r"(a[1]), "r"(a[2]), "r"(a[3]), "r"(b[0]), "r"(b[1]));
}

__device__ __forceinline__ uint32_t tf32r(float x) {
    uint32_t u;
    asm("cvt.rna.tf32.f32 %0, %1;" : "=r"(u) : "f"(x));
    return u;
}

// ---------------------------------------------------------------------------
// Shared GEMM config: C[M,N] = A[M,K] * B[N,K]^T, 128x128 tile, 256 thr
// ---------------------------------------------------------------------------
#define APITCH 36
#define STAGE_BYTES (128 * APITCH * 4)
#define GEMM_SMEM (4 * STAGE_BYTES)

#define GEMM_LOAD_TILE(s, kt, Abase, Bbase, K)                                 \
    do {                                                                       \
        const float* Ag = (Abase) + (size_t)bm * (K) + (kt) * 32;              \
        const float* Bg = (Bbase) + (size_t)bn * (K) + (kt) * 32;              \
        uint32_t adst = sbase + (s) * STAGE_BYTES;                             \
        uint32_t bdst = sbase + 2 * STAGE_BYTES + (s) * STAGE_BYTES;           \
        _Pragma("unroll")                                                      \
        for (int i = 0; i < 4; i++) {                                          \
            int idx = tid + i * 256;                                           \
            int row = idx >> 3, c4 = idx & 7;                                  \
            CP16(adst + row * 144 + c4 * 16, Ag + (size_t)row * (K) + c4 * 4); \
            CP16(bdst + row * 144 + c4 * 16, Bg + (size_t)row * (K) + c4 * 4); \
        }                                                                      \
    } while (0)

#define GEMM_MAINLOOP(Abase, Bbase, K)                                         \
    const int NK = (K) >> 5;                                                   \
    GEMM_LOAD_TILE(0, 0, Abase, Bbase, K);                                     \
    CP_COMMIT();                                                               \
    for (int kt = 0; kt < NK; kt++) {                                          \
        if (kt + 1 < NK) {                                                     \
            GEMM_LOAD_TILE((kt + 1) & 1, kt + 1, Abase, Bbase, K);             \
            CP_COMMIT();                                                       \
            CP_WAIT(1);                                                        \
        } else {                                                               \
            CP_WAIT(0);                                                        \
        }                                                                      \
        __syncthreads();                                                       \
        const uint32_t* as = (const uint32_t*)(sh + (kt & 1) * STAGE_BYTES);   \
        const uint32_t* bs = (const uint32_t*)(sh + 2 * STAGE_BYTES + (kt & 1) * STAGE_BYTES); \
        _Pragma("unroll")                                                      \
        for (int ks = 0; ks < 4; ks++) {                                       \
            const int kc = ks * 8 + (lane & 3);                                \
            uint32_t af[4][4], bf[4][2];                                       \
            _Pragma("unroll")                                                  \
            for (int mi = 0; mi < 4; mi++) {                                   \
                int r = warp_m * 64 + mi * 16 + (lane >> 2);                   \
                af[mi][0] = as[r * APITCH + kc];                               \
                af[mi][1] = as[(r + 8) * APITCH + kc];                         \
                af[mi][2] = as[r * APITCH + kc + 4];                           \
                af[mi][3] = as[(r + 8) * APITCH + kc + 4];                     \
            }                                                                  \
            _Pragma("unroll")                                                  \
            for (int ni = 0; ni < 4; ni++) {                                   \
                int n = warp_n * 32 + ni * 8 + (lane >> 2);                    \
                bf[ni][0] = bs[n * APITCH + kc];                               \
                bf[ni][1] = bs[n * APITCH + kc + 4];                           \
            }                                                                  \
            _Pragma("unroll")                                                  \
            for (int mi = 0; mi < 4; mi++)                                     \
                _Pragma("unroll")                                              \
                for (int ni = 0; ni < 4; ni++)                                 \
                    mma_tf32(c[mi][ni], af[mi], bf[ni]);                       \
        }                                                                      \
        __syncthreads();                                                       \
    }

// ---------------------------------------------------------------------------
// Fused QKV GEMM: one launch computes q,k,v; RoPE fused for q,k; v tf32-rounded
// grid (24, 32): blockIdx.x>>3 selects {q,k,v}
// ---------------------------------------------------------------------------
__global__ __launch_bounds__(256) void gemm_qkv(
    const float* __restrict__ A, const float* __restrict__ Wbase,
    float* __restrict__ q, float* __restrict__ k, float* __restrict__ v)
{
    extern __shared__ char sh[];
    const uint32_t sbase = smem_u32(sh);
    const int tid  = threadIdx.x;
    const int lane = tid & 31;
    const int wid  = tid >> 5;
    const int warp_m = wid >> 2;
    const int warp_n = wid & 3;
    const int which = blockIdx.x >> 3;          // 0=q,1=k,2=v
    const int bm = blockIdx.y * 128;
    const int bn = (blockIdx.x & 7) * 128;
    const float* B = Wbase + (size_t)which * DIM * DIM;
    float* C = (which == 0) ? q : (which == 1) ? k : v;

    float c[4][4][4];
    #pragma unroll
    for (int i = 0; i < 4; i++)
        #pragma unroll
        for (int j = 0; j < 4; j++)
            #pragma unroll
            for (int kk = 0; kk < 4; kk++) c[i][j][kk] = 0.0f;

    GEMM_MAINLOOP(A, B, DIM);

    // Epilogue: rope-rotate (q,k) or round (v), store tf32
    #pragma unroll
    for (int mi = 0; mi < 4; mi++) {
        int r0 = bm + warp_m * 64 + mi * 16 + (lane >> 2);
        #pragma unroll
        for (int ni = 0; ni < 4; ni++) {
            int col = bn + warp_n * 32 + ni * 8 + 2 * (lane & 3);
            float* cc = c[mi][ni];
            if (which < 2) {
                int p = (col & 63) >> 1;
                float c0 = g_cos[r0 * 32 + p],       s0 = g_sin[r0 * 32 + p];
                float c1 = g_cos[(r0 + 8) * 32 + p], s1 = g_sin[(r0 + 8) * 32 + p];
                float y0 = cc[0] * c0 - cc[1] * s0;
                float y1 = cc[1] * c0 + cc[0] * s0;
                float y2 = cc[2] * c1 - cc[3] * s1;
                float y3 = cc[3] * c1 + cc[2] * s1;
                *(float2*)(C + (size_t)r0 * DIM + col) = make_float2(
                    __uint_as_float(tf32r(y0)), __uint_as_float(tf32r(y1)));
                *(float2*)(C + (size_t)(r0 + 8) * DIM + col) = make_float2(
                    __uint_as_float(tf32r(y2)), __uint_as_float(tf32r(y3)));
            } else {
                *(float2*)(C + (size_t)r0 * DIM + col) = make_float2(
                    __uint_as_float(tf32r(cc[0])), __uint_as_float(tf32r(cc[1])));
                *(float2*)(C + (size_t)(r0 + 8) * DIM + col) = make_float2(
                    __uint_as_float(tf32r(cc[2])), __uint_as_float(tf32r(cc[3])));
            }
        }
    }
}

// ---------------------------------------------------------------------------
// Plain GEMM (for Wo), fp32 output
// ---------------------------------------------------------------------------
__global__ __launch_bounds__(256) void gemm_mma(
    const float* __restrict__ A, const float* __restrict__ B,
    float* __restrict__ C, int M, int N, int K)
{
    extern __shared__ char sh[];
    const uint32_t sbase = smem_u32(sh);
    const int tid  = threadIdx.x;
    const int lane = tid & 31;
    const int wid  = tid >> 5;
    const int warp_m = wid >> 2;
    const int warp_n = wid & 3;
    const int bm = blockIdx.y * 128;
    const int bn = blockIdx.x * 128;

    float c[4][4][4];
    #pragma unroll
    for (int i = 0; i < 4; i++)
        #pragma unroll
        for (int j = 0; j < 4; j++)
            #pragma unroll
            for (int kk = 0; kk < 4; kk++) c[i][j][kk] = 0.0f;

    GEMM_MAINLOOP(A, B, K);

    #pragma unroll
    for (int mi = 0; mi < 4; mi++) {
        int r0 = bm + warp_m * 64 + mi * 16 + (lane >> 2);
        #pragma unroll
        for (int ni = 0; ni < 4; ni++) {
            int col = bn + warp_n * 32 + ni * 8 + 2 * (lane & 3);
            *(float2*)(C + (size_t)r0 * N + col) =
                make_float2(c[mi][ni][0], c[mi][ni][1]);
            *(float2*)(C + (size_t)(r0 + 8) * N + col) =
                make_float2(c[mi][ni][2], c[mi][ni][3]);
        }
    }
}

// ---------------------------------------------------------------------------
// Rounding kernels
// ---------------------------------------------------------------------------
__global__ void round_tf32_kernel(const float4* __restrict__ in,
                                  float4* __restrict__ out, int n4)
{
    int i = blockIdx.x * blockDim.x + threadIdx.x;
    if (i >= n4) return;
    float4 v = in[i];
    out[i] = make_float4(__uint_as_float(tf32r(v.x)), __uint_as_float(tf32r(v.y)),
                         __uint_as_float(tf32r(v.z)), __uint_as_float(tf32r(v.w)));
}

// All four weight matrices in one launch (grid = 4 * 1024 blocks)
__global__ void round_w_kernel(const float4* __restrict__ w0,
                               const float4* __restrict__ w1,
                               const float4* __restrict__ w2,
                               const float4* __restrict__ w3,
                               float4* __restrict__ out)
{
    const int per = DIM * DIM / 4;          // 262144 float4 per matrix
    int i = blockIdx.x * blockDim.x + threadIdx.x;
    int which = i / per;
    int off = i - which * per;
    const float4* src = (which == 0) ? w0 : (which == 1) ? w1 : (which == 2) ? w2 : w3;
    float4 v = src[off];
    out[i] = make_float4(__uint_as_float(tf32r(v.x)), __uint_as_float(tf32r(v.y)),
                         __uint_as_float(tf32r(v.z)), __uint_as_float(tf32r(v.w)));
}

// ---------------------------------------------------------------------------
// RoPE table: double mul + double range reduction + float sincos
// ---------------------------------------------------------------------------
__global__ void rope_table_kernel()
{
    int idx = blockIdx.x * blockDim.x + threadIdx.x;
    if (idx >= S_LEN * HALF_HD) return;
    int s = idx / HALF_HD;
    int p = idx % HALF_HD;
    double inv = exp((double)p * -0.28782313662425572);   // -ln(10000)/32
    double ang = (double)s * inv;
    double t = floor(ang * 0.15915494309189535);          // 1/(2*pi)
    float r = (float)(ang - t * 6.283185307179586);
    float sn, cs;
    sincosf(r, &sn, &cs);
    g_cos[idx] = cs;
    g_sin[idx] = sn;
}

// ---------------------------------------------------------------------------
// Tensor-core causal flash attention (validated R5 version, unchanged)
// ---------------------------------------------------------------------------
#define KSP 68
#define VSP 72
#define PSP 68
#define FA_KS_BYTES (64 * KSP * 4)
#define FA_VS_BYTES (64 * VSP * 4)
#define FA_VS_OFF   (2 * FA_KS_BYTES)
#define FA_P_OFF    (2 * FA_KS_BYTES + 2 * FA_VS_BYTES)
#define FA_SMEM     (FA_P_OFF + 128 * PSP * 4)

__global__ __launch_bounds__(256, 2) void flash_tc_kernel()
{
    extern __shared__ char sh[];
    float* shf = (float*)sh;
    const uint32_t sbase = smem_u32(sh);
    const int tid  = threadIdx.x;
    const int lane = tid & 31;
    const int w    = tid >> 5;
    const int quad = lane >> 2;
    const int qj   = lane & 3;
    const int qt   = 31 - blockIdx.x;
    const int h    = blockIdx.y;

    const int row_a  = 16 * w + quad;
    const int qrow_a = qt * 128 + row_a;
    const int qrow_b = qrow_a + 8;

    uint32_t qa[8][4];
    {
        const float* qpa = g_q + (size_t)qrow_a * DIM + h * HD;
        const float* qpb = g_q + (size_t)qrow_b * DIM + h * HD;
        #pragma unroll
        for (int ks = 0; ks < 8; ks++) {
            int kc = ks * 8 + qj;
            qa[ks][0] = __float_as_uint(qpa[kc] * 0.125f);
            qa[ks][1] = __float_as_uint(qpb[kc] * 0.125f);
            qa[ks][2] = __float_as_uint(qpa[kc + 4] * 0.125f);
            qa[ks][3] = __float_as_uint(qpb[kc + 4] * 0.125f);
        }
    }

    float o[8][4];
    #pragma unroll
    for (int nb = 0; nb < 8; nb++)
        #pragma unroll
        for (int i = 0; i < 4; i++) o[nb][i] = 0.0f;

    float m_a = -1e30f, m_b = -1e30f, l_a = 0.0f, l_b = 0.0f;

    const int nkt = 2 * qt + 2;

    #define FA_LOAD(kt, b) do {                                               \
        const float* Kg = g_k + (size_t)(kt) * 64 * DIM + h * HD;             \
        const float* Vg = g_v + (size_t)(kt) * 64 * DIM + h * HD;             \
        uint32_t kd = sbase + (b) * FA_KS_BYTES;                              \
        uint32_t vd = sbase + FA_VS_OFF + (b) * FA_VS_BYTES;                  \
        _Pragma("unroll")                                                     \
        for (int i = 0; i < 4; i++) {                                         \
            int idx = tid + i * 256;                                          \
            int r = idx >> 4, c4 = idx & 15;                                  \
            CP16(kd + r * (KSP * 4) + c4 * 16, Kg + (size_t)r * DIM + c4 * 4);\
            CP16(vd + r * (VSP * 4) + c4 * 16, Vg + (size_t)r * DIM + c4 * 4);\
        }                                                                     \
    } while (0)

    FA_LOAD(0, 0);
    CP_COMMIT();

    float* Pw = shf + FA_P_OFF / 4 + 16 * w * PSP;

    for (int kt = 0; kt < nkt; kt++) {
        if (kt + 1 < nkt) {
            FA_LOAD(kt + 1, (kt + 1) & 1);
            CP_COMMIT();
            CP_WAIT(1);
        } else {
            CP_WAIT(0);
        }
        __syncthreads();

        const float* Ks = shf + (kt & 1) * (FA_KS_BYTES / 4);
        const float* Vs = shf + FA_VS_OFF / 4 + (kt & 1) * (FA_VS_BYTES / 4);

        float s[8][4];
        #pragma unroll
        for (int nb = 0; nb < 8; nb++)
            #pragma unroll
            for (int i = 0; i < 4; i++) s[nb][i] = 0.0f;

        #pragma unroll
        for (int ks = 0; ks < 8; ks++) {
            const int kc = ks * 8 + qj;
            #pragma unroll
            for (int nb = 0; nb < 8; nb++) {
                uint32_t b[2];
                b[0] = __float_as_uint(Ks[(8 * nb + quad) * KSP + kc]);
                b[1] = __float_as_uint(Ks[(8 * nb + quad) * KSP + kc + 4]);
                mma_tf32(s[nb], qa[ks], b);
            }
        }

        if (kt >= 2 * qt) {
            #pragma unroll
            for (int nb = 0; nb < 8; nb++) {
                int col = kt * 64 + 8 * nb + 2 * qj;
                if (col > qrow_a)     s[nb][0] = -1e30f;
                if (col + 1 > qrow_a) s[nb][1] = -1e30f;
                if (col > qrow_b)     s[nb][2] = -1e30f;
                if (col + 1 > qrow_b) s[nb][3] = -1e30f;
            }
        }

        float tma = -1e30f, tmb = -1e30f;
        #pragma unroll
        for (int nb = 0; nb < 8; nb++) {
            tma = fmaxf(tma, fmaxf(s[nb][0], s[nb][1]));
            tmb = fmaxf(tmb, fmaxf(s[nb][2], s[nb][3]));
        }
        tma = fmaxf(tma, __shfl_xor_sync(0xFFFFFFFF, tma, 1));
        tma = fmaxf(tma, __shfl_xor_sync(0xFFFFFFFF, tma, 2));
        tmb = fmaxf(tmb, __shfl_xor_sync(0xFFFFFFFF, tmb, 1));
        tmb = fmaxf(tmb, __shfl_xor_sync(0xFFFFFFFF, tmb, 2));

        float mna = fmaxf(m_a, tma);
        float mnb = fmaxf(m_b, tmb);
        float aa = __expf(m_a - mna);
        float ab = __expf(m_b - mnb);
        m_a = mna; m_b = mnb;
        l_a *= aa;  l_b *= ab;
        #pragma unroll
        for (int nb = 0; nb < 8; nb++) {
            o[nb][0] *= aa; o[nb][1] *= aa;
            o[nb][2] *= ab; o[nb][3] *= ab;
        }

        #pragma unroll
        for (int nb = 0; nb < 8; nb++) {
            float p0 = __expf(s[nb][0] - m_a);
            float p1 = __expf(s[nb][1] - m_a);
            float p2 = __expf(s[nb][2] - m_b);
            float p3 = __expf(s[nb][3] - m_b);
            l_a += p0 + p1;
            l_b += p2 + p3;
            int cc = 8 * nb + 2 * qj;
            *(float2*)&Pw[quad * PSP + cc] =
                make_float2(__uint_as_float(tf32r(p0)), __uint_as_float(tf32r(p1)));
            *(float2*)&Pw[(quad + 8) * PSP + cc] =
                make_float2(__uint_as_float(tf32r(p2)), __uint_as_float(tf32r(p3)));
        }
        __syncwarp();

        #pragma unroll
        for (int ks = 0; ks < 8; ks++) {
            const int kc = ks * 8 + qj;
            uint32_t a[4];
            a[0] = __float_as_uint(Pw[quad * PSP + kc]);
            a[1] = __float_as_uint(Pw[(quad + 8) * PSP + kc]);
            a[2] = __float_as_uint(Pw[quad * PSP + kc + 4]);
            a[3] = __float_as_uint(Pw[(quad + 8) * PSP + kc + 4]);
            #pragma unroll
            for (int nb = 0; nb < 8; nb++) {
                uint32_t b[2];
                b[0] = __float_as_uint(Vs[kc * VSP + 8 * nb + quad]);
                b[1] = __float_as_uint(Vs[(kc + 4) * VSP + 8 * nb + quad]);
                mma_tf32(o[nb], a, b);
            }
        }
        __syncthreads();
    }

    l_a += __shfl_xor_sync(0xFFFFFFFF, l_a, 1);
    l_a += __shfl_xor_sync(0xFFFFFFFF, l_a, 2);
    l_b += __shfl_xor_sync(0xFFFFFFFF, l_b, 1);
    l_b += __shfl_xor_sync(0xFFFFFFFF, l_b, 2);
    float ia = 1.0f / l_a;
    float ib = 1.0f / l_b;

    float* oa = g_o + (size_t)qrow_a * DIM + h * HD;
    float* ob = g_o + (size_t)qrow_b * DIM + h * HD;
    #pragma unroll
    for (int nb = 0; nb < 8; nb++) {
        int cc = 8 * nb + 2 * qj;
        *(float2*)(oa + cc) = make_float2(
            __uint_as_float(tf32r(o[nb][0] * ia)),
            __uint_as_float(tf32r(o[nb][1] * ia)));
        *(float2*)(ob + cc) = make_float2(
            __uint_as_float(tf32r(o[nb][2] * ib)),
            __uint_as_float(tf32r(o[nb][3] * ib)));
    }
}

// ---------------------------------------------------------------------------
// Launch
// ---------------------------------------------------------------------------
extern "C" void kernel_launch(void* const* d_in, const int* in_sizes, int n_in,
                              void* d_out, int out_size)
{
    const float* x  = (const float*)d_in[0];
    const float* Wq = (const float*)d_in[1];
    const float* Wk = (const float*)d_in[2];
    const float* Wv = (const float*)d_in[3];
    const float* Wo = (const float*)d_in[4];
    float* out = (float*)d_out;

    float *gq, *gk, *gv, *go, *gxr, *gwr;
    cudaGetSymbolAddress((void**)&gq, g_q);
    cudaGetSymbolAddress((void**)&gk, g_k);
    cudaGetSymbolAddress((void**)&gv, g_v);
    cudaGetSymbolAddress((void**)&go, g_o);
    cudaGetSymbolAddress((void**)&gxr, g_xr);
    cudaGetSymbolAddress((void**)&gwr, g_wr);

    cudaFuncSetAttribute(gemm_qkv,
                         cudaFuncAttributeMaxDynamicSharedMemorySize, GEMM_SMEM);
    cudaFuncSetAttribute(gemm_mma,
                         cudaFuncAttributeMaxDynamicSharedMemorySize, GEMM_SMEM);
    cudaFuncSetAttribute(flash_tc_kernel,
                         cudaFuncAttributeMaxDynamicSharedMemorySize, FA_SMEM);

    const int XW4 = S_LEN * DIM / 4;
    round_tf32_kernel<<<(XW4 + 255) / 256, 256>>>((const float4*)x, (float4*)gxr, XW4);
    round_w_kernel<<<4 * 1024, 256>>>((const float4*)Wq, (const float4*)Wk,
                                      (const float4*)Wv, (const float4*)Wo,
                                      (float4*)gwr);
    rope_table_kernel<<<(S_LEN * HALF_HD + 255) / 256, 256>>>();

    gemm_qkv<<<dim3(24, 32), 256, GEMM_SMEM>>>(gxr, gwr, gq, gk, gv);

    flash_tc_kernel<<<dim3(32, NH), 256, FA_SMEM>>>();

    gemm_mma<<<dim3(8, 32), 256, GEMM_SMEM>>>(go, gwr + 3 * DIM * DIM, out,
                                              S_LEN, DIM, DIM);
}

// round 13
// speedup vs baseline: 1.1360x; 1.1360x over previous
#include <cuda_runtime.h>
#include <cstdint>
#include <math.h>

#define S_LEN 4096
#define DIM 1024
#define NH 16
#define HD 64
#define HALF_HD 32

// ---------------------------------------------------------------------------
// Scratch (allocation-free)
// ---------------------------------------------------------------------------
__device__ float g_q[S_LEN * DIM];
__device__ float g_k[S_LEN * DIM];
__device__ float g_v[S_LEN * DIM];
__device__ float g_o[S_LEN * DIM];
__device__ float g_xr[S_LEN * DIM];
__device__ float g_wr[4 * DIM * DIM];
__device__ float g_cos[S_LEN * HALF_HD];
__device__ float g_sin[S_LEN * HALF_HD];

// ---------------------------------------------------------------------------
// Helpers
// ---------------------------------------------------------------------------
__device__ __forceinline__ uint32_t smem_u32(const void* p) {
    uint32_t a;
    asm("{ .reg .u64 t; cvta.to.shared.u64 t, %1; cvt.u32.u64 %0, t; }"
        : "=r"(a) : "l"(p));
    return a;
}

#define CP16(dst, src) \
    asm volatile("cp.async.cg.shared.global [%0], [%1], 16;" :: "r"(dst), "l"(src))
#define CP_COMMIT() asm volatile("cp.async.commit_group;" ::: "memory")
#define CP_WAIT(n)  asm volatile("cp.async.wait_group %0;" :: "n"(n) : "memory")

__device__ __forceinline__ void mma_tf32(float* c, const uint32_t* a, const uint32_t* b)
{
    asm volatile(
        "mma.sync.aligned.m16n8k8.row.col.f32.tf32.tf32.f32 "
        "{%0,%1,%2,%3}, {%4,%5,%6,%7}, {%8,%9}, {%0,%1,%2,%3};"
        : "+f"(c[0]), "+f"(c[1]), "+f"(c[2]), "+f"(c[3])
        : "r"(a[0]), "r"(a[1]), "r"(a[2]), "r"(a[3]), "r"(b[0]), "r"(b[1]));
}

__device__ __forceinline__ uint32_t tf32r(float x) {
    uint32_t u;
    asm("cvt.rna.tf32.f32 %0, %1;" : "=r"(u) : "f"(x));
    return u;
}

// ---------------------------------------------------------------------------
// GEMM config: C[M,N] = A[M,K] * B[N,K]^T, CTA tile 128x128, 128 threads,
// 4 warps (2x2), warp tile 64x64. BK=32, 2-stage cp.async.
// ---------------------------------------------------------------------------
#define APITCH 36
#define STAGE_BYTES (128 * APITCH * 4)
#define GEMM_SMEM (4 * STAGE_BYTES)

#define GEMM_LOAD_TILE(s, kt, Abase, Bbase, K)                                 \
    do {                                                                       \
        const float* Ag = (Abase) + (size_t)bm * (K) + (kt) * 32;              \
        const float* Bg = (Bbase) + (size_t)bn * (K) + (kt) * 32;              \
        uint32_t adst = sbase + (s) * STAGE_BYTES;                             \
        uint32_t bdst = sbase + 2 * STAGE_BYTES + (s) * STAGE_BYTES;           \
        _Pragma("unroll")                                                      \
        for (int i = 0; i < 8; i++) {                                          \
            int idx = tid + i * 128;                                           \
            int row = idx >> 3, c4 = idx & 7;                                  \
            CP16(adst + row * 144 + c4 * 16, Ag + (size_t)row * (K) + c4 * 4); \
            CP16(bdst + row * 144 + c4 * 16, Bg + (size_t)row * (K) + c4 * 4); \
        }                                                                      \
    } while (0)

#define GEMM_MAINLOOP(Abase, Bbase, K)                                         \
    const int NK = (K) >> 5;                                                   \
    GEMM_LOAD_TILE(0, 0, Abase, Bbase, K);                                     \
    CP_COMMIT();                                                               \
    for (int kt = 0; kt < NK; kt++) {                                          \
        if (kt + 1 < NK) {                                                     \
            GEMM_LOAD_TILE((kt + 1) & 1, kt + 1, Abase, Bbase, K);             \
            CP_COMMIT();                                                       \
            CP_WAIT(1);                                                        \
        } else {                                                               \
            CP_WAIT(0);                                                        \
        }                                                                      \
        __syncthreads();                                                       \
        const uint32_t* as = (const uint32_t*)(sh + (kt & 1) * STAGE_BYTES);   \
        const uint32_t* bs = (const uint32_t*)(sh + 2 * STAGE_BYTES + (kt & 1) * STAGE_BYTES); \
        _Pragma("unroll")                                                      \
        for (int ks = 0; ks < 4; ks++) {                                       \
            const int kc = ks * 8 + (lane & 3);                                \
            uint32_t af[4][4], bf[8][2];                                       \
            _Pragma("unroll")                                                  \
            for (int mi = 0; mi < 4; mi++) {                                   \
                int r = warp_m * 64 + mi * 16 + (lane >> 2);                   \
                af[mi][0] = as[r * APITCH + kc];                               \
                af[mi][1] = as[(r + 8) * APITCH + kc];                         \
                af[mi][2] = as[r * APITCH + kc + 4];                           \
                af[mi][3] = as[(r + 8) * APITCH + kc + 4];                     \
            }                                                                  \
            _Pragma("unroll")                                                  \
            for (int ni = 0; ni < 8; ni++) {                                   \
                int n = warp_n * 64 + ni * 8 + (lane >> 2);                    \
                bf[ni][0] = bs[n * APITCH + kc];                               \
                bf[ni][1] = bs[n * APITCH + kc + 4];                           \
            }                                                                  \
            _Pragma("unroll")                                                  \
            for (int mi = 0; mi < 4; mi++)                                     \
                _Pragma("unroll")                                              \
                for (int ni = 0; ni < 8; ni++)                                 \
                    mma_tf32(c[mi][ni], af[mi], bf[ni]);                       \
        }                                                                      \
        __syncthreads();                                                       \
    }

// ---------------------------------------------------------------------------
// Fused QKV GEMM: grid (24, 32): blockIdx.x>>3 selects {q,k,v}
// ---------------------------------------------------------------------------
__global__ __launch_bounds__(128) void gemm_qkv(
    const float* __restrict__ A, const float* __restrict__ Wbase,
    float* __restrict__ q, float* __restrict__ k, float* __restrict__ v)
{
    extern __shared__ char sh[];
    const uint32_t sbase = smem_u32(sh);
    const int tid  = threadIdx.x;
    const int lane = tid & 31;
    const int wid  = tid >> 5;
    const int warp_m = wid >> 1;    // 0..1
    const int warp_n = wid & 1;     // 0..1
    const int which = blockIdx.x >> 3;
    const int bm = blockIdx.y * 128;
    const int bn = (blockIdx.x & 7) * 128;
    const float* B = Wbase + (size_t)which * DIM * DIM;
    float* C = (which == 0) ? q : (which == 1) ? k : v;

    float c[4][8][4];
    #pragma unroll
    for (int i = 0; i < 4; i++)
        #pragma unroll
        for (int j = 0; j < 8; j++)
            #pragma unroll
            for (int kk = 0; kk < 4; kk++) c[i][j][kk] = 0.0f;

    GEMM_MAINLOOP(A, B, DIM);

    #pragma unroll
    for (int mi = 0; mi < 4; mi++) {
        int r0 = bm + warp_m * 64 + mi * 16 + (lane >> 2);
        #pragma unroll
        for (int ni = 0; ni < 8; ni++) {
            int col = bn + warp_n * 64 + ni * 8 + 2 * (lane & 3);
            float* cc = c[mi][ni];
            if (which < 2) {
                int p = (col & 63) >> 1;
                float c0 = g_cos[r0 * 32 + p],       s0 = g_sin[r0 * 32 + p];
                float c1 = g_cos[(r0 + 8) * 32 + p], s1 = g_sin[(r0 + 8) * 32 + p];
                float y0 = cc[0] * c0 - cc[1] * s0;
                float y1 = cc[1] * c0 + cc[0] * s0;
                float y2 = cc[2] * c1 - cc[3] * s1;
                float y3 = cc[3] * c1 + cc[2] * s1;
                *(float2*)(C + (size_t)r0 * DIM + col) = make_float2(
                    __uint_as_float(tf32r(y0)), __uint_as_float(tf32r(y1)));
                *(float2*)(C + (size_t)(r0 + 8) * DIM + col) = make_float2(
                    __uint_as_float(tf32r(y2)), __uint_as_float(tf32r(y3)));
            } else {
                *(float2*)(C + (size_t)r0 * DIM + col) = make_float2(
                    __uint_as_float(tf32r(cc[0])), __uint_as_float(tf32r(cc[1])));
                *(float2*)(C + (size_t)(r0 + 8) * DIM + col) = make_float2(
                    __uint_as_float(tf32r(cc[2])), __uint_as_float(tf32r(cc[3])));
            }
        }
    }
}

// ---------------------------------------------------------------------------
// Plain GEMM (Wo), fp32 output
// ---------------------------------------------------------------------------
__global__ __launch_bounds__(128) void gemm_mma(
    const float* __restrict__ A, const float* __restrict__ B,
    float* __restrict__ C, int M, int N, int K)
{
    extern __shared__ char sh[];
    const uint32_t sbase = smem_u32(sh);
    const int tid  = threadIdx.x;
    const int lane = tid & 31;
    const int wid  = tid >> 5;
    const int warp_m = wid >> 1;
    const int warp_n = wid & 1;
    const int bm = blockIdx.y * 128;
    const int bn = blockIdx.x * 128;

    float c[4][8][4];
    #pragma unroll
    for (int i = 0; i < 4; i++)
        #pragma unroll
        for (int j = 0; j < 8; j++)
            #pragma unroll
            for (int kk = 0; kk < 4; kk++) c[i][j][kk] = 0.0f;

    GEMM_MAINLOOP(A, B, K);

    #pragma unroll
    for (int mi = 0; mi < 4; mi++) {
        int r0 = bm + warp_m * 64 + mi * 16 + (lane >> 2);
        #pragma unroll
        for (int ni = 0; ni < 8; ni++) {
            int col = bn + warp_n * 64 + ni * 8 + 2 * (lane & 3);
            *(float2*)(C + (size_t)r0 * N + col) =
                make_float2(c[mi][ni][0], c[mi][ni][1]);
            *(float2*)(C + (size_t)(r0 + 8) * N + col) =
                make_float2(c[mi][ni][2], c[mi][ni][3]);
        }
    }
}

// ---------------------------------------------------------------------------
// Rounding kernels
// ---------------------------------------------------------------------------
__global__ void round_tf32_kernel(const float4* __restrict__ in,
                                  float4* __restrict__ out, int n4)
{
    int i = blockIdx.x * blockDim.x + threadIdx.x;
    if (i >= n4) return;
    float4 v = in[i];
    out[i] = make_float4(__uint_as_float(tf32r(v.x)), __uint_as_float(tf32r(v.y)),
                         __uint_as_float(tf32r(v.z)), __uint_as_float(tf32r(v.w)));
}

__global__ void round_w_kernel(const float4* __restrict__ w0,
                               const float4* __restrict__ w1,
                               const float4* __restrict__ w2,
                               const float4* __restrict__ w3,
                               float4* __restrict__ out)
{
    const int per = DIM * DIM / 4;
    int i = blockIdx.x * blockDim.x + threadIdx.x;
    int which = i / per;
    int off = i - which * per;
    const float4* src = (which == 0) ? w0 : (which == 1) ? w1 : (which == 2) ? w2 : w3;
    float4 v = src[off];
    out[i] = make_float4(__uint_as_float(tf32r(v.x)), __uint_as_float(tf32r(v.y)),
                         __uint_as_float(tf32r(v.z)), __uint_as_float(tf32r(v.w)));
}

// ---------------------------------------------------------------------------
// RoPE table
// ---------------------------------------------------------------------------
__global__ void rope_table_kernel()
{
    int idx = blockIdx.x * blockDim.x + threadIdx.x;
    if (idx >= S_LEN * HALF_HD) return;
    int s = idx / HALF_HD;
    int p = idx % HALF_HD;
    double inv = exp((double)p * -0.28782313662425572);
    double ang = (double)s * inv;
    double t = floor(ang * 0.15915494309189535);
    float r = (float)(ang - t * 6.283185307179586);
    float sn, cs;
    sincosf(r, &sn, &cs);
    g_cos[idx] = cs;
    g_sin[idx] = sn;
}

// ---------------------------------------------------------------------------
// Tensor-core causal flash attention. 128 threads, 4 warps x 32 q-rows.
// Each B fragment (K or V) feeds 2 MMAs (two m-groups) -> half the LDS/MMA.
// ---------------------------------------------------------------------------
#define KSP 68
#define VSP 72
#define PSP 68
#define FA_KS_BYTES (64 * KSP * 4)
#define FA_VS_BYTES (64 * VSP * 4)
#define FA_VS_OFF   (2 * FA_KS_BYTES)
#define FA_P_OFF    (2 * FA_KS_BYTES + 2 * FA_VS_BYTES)
#define FA_SMEM     (FA_P_OFF + 128 * PSP * 4)

__global__ __launch_bounds__(128, 2) void flash_tc_kernel()
{
    extern __shared__ char sh[];
    float* shf = (float*)sh;
    const uint32_t sbase = smem_u32(sh);
    const int tid  = threadIdx.x;
    const int lane = tid & 31;
    const int w    = tid >> 5;      // 0..3
    const int quad = lane >> 2;
    const int qj   = lane & 3;
    const int qt   = 31 - blockIdx.x;
    const int h    = blockIdx.y;

    // warp covers 32 q-rows: groups at +0,+8 (m-group 0) and +16,+24 (m-group 1)
    const int qrow = qt * 128 + 32 * w + quad;

    uint32_t qa0[8][4], qa1[8][4];
    {
        const float* qp = g_q + (size_t)qrow * DIM + h * HD;
        #pragma unroll
        for (int ks = 0; ks < 8; ks++) {
            int kc = ks * 8 + qj;
            qa0[ks][0] = __float_as_uint(qp[kc] * 0.125f);
            qa0[ks][1] = __float_as_uint(qp[8 * DIM + kc] * 0.125f);
            qa0[ks][2] = __float_as_uint(qp[kc + 4] * 0.125f);
            qa0[ks][3] = __float_as_uint(qp[8 * DIM + kc + 4] * 0.125f);
            qa1[ks][0] = __float_as_uint(qp[16 * DIM + kc] * 0.125f);
            qa1[ks][1] = __float_as_uint(qp[24 * DIM + kc] * 0.125f);
            qa1[ks][2] = __float_as_uint(qp[16 * DIM + kc + 4] * 0.125f);
            qa1[ks][3] = __float_as_uint(qp[24 * DIM + kc + 4] * 0.125f);
        }
    }

    float o0[8][4], o1[8][4];
    #pragma unroll
    for (int nb = 0; nb < 8; nb++)
        #pragma unroll
        for (int i = 0; i < 4; i++) { o0[nb][i] = 0.0f; o1[nb][i] = 0.0f; }

    float m0a = -1e30f, m0b = -1e30f, m1a = -1e30f, m1b = -1e30f;
    float l0a = 0.0f, l0b = 0.0f, l1a = 0.0f, l1b = 0.0f;

    const int nkt = 2 * qt + 2;

    #define FA_LOAD(kt, b) do {                                               \
        const float* Kg = g_k + (size_t)(kt) * 64 * DIM + h * HD;             \
        const float* Vg = g_v + (size_t)(kt) * 64 * DIM + h * HD;             \
        uint32_t kd = sbase + (b) * FA_KS_BYTES;                              \
        uint32_t vd = sbase + FA_VS_OFF + (b) * FA_VS_BYTES;                  \
        _Pragma("unroll")                                                     \
        for (int i = 0; i < 8; i++) {                                         \
            int idx = tid + i * 128;                                          \
            int r = idx >> 4, c4 = idx & 15;                                  \
            CP16(kd + r * (KSP * 4) + c4 * 16, Kg + (size_t)r * DIM + c4 * 4);\
            CP16(vd + r * (VSP * 4) + c4 * 16, Vg + (size_t)r * DIM + c4 * 4);\
        }                                                                     \
    } while (0)

    FA_LOAD(0, 0);
    CP_COMMIT();

    float* Pw = shf + FA_P_OFF / 4 + 32 * w * PSP;   // warp-private 32 rows

    for (int kt = 0; kt < nkt; kt++) {
        if (kt + 1 < nkt) {
            FA_LOAD(kt + 1, (kt + 1) & 1);
            CP_COMMIT();
            CP_WAIT(1);
        } else {
            CP_WAIT(0);
        }
        __syncthreads();

        const float* Ks = shf + (kt & 1) * (FA_KS_BYTES / 4);
        const float* Vs = shf + FA_VS_OFF / 4 + (kt & 1) * (FA_VS_BYTES / 4);

        // ---- S = (Q/8) K^T ----
        float s0[8][4], s1[8][4];
        #pragma unroll
        for (int nb = 0; nb < 8; nb++)
            #pragma unroll
            for (int i = 0; i < 4; i++) { s0[nb][i] = 0.0f; s1[nb][i] = 0.0f; }

        #pragma unroll
        for (int ks = 0; ks < 8; ks++) {
            const int kc = ks * 8 + qj;
            #pragma unroll
            for (int nb = 0; nb < 8; nb++) {
                uint32_t b[2];
                b[0] = __float_as_uint(Ks[(8 * nb + quad) * KSP + kc]);
                b[1] = __float_as_uint(Ks[(8 * nb + quad) * KSP + kc + 4]);
                mma_tf32(s0[nb], qa0[ks], b);
                mma_tf32(s1[nb], qa1[ks], b);
            }
        }

        // ---- causal mask ----
        if (kt >= 2 * qt) {
            #pragma unroll
            for (int nb = 0; nb < 8; nb++) {
                int col = kt * 64 + 8 * nb + 2 * qj;
                if (col > qrow)          s0[nb][0] = -1e30f;
                if (col + 1 > qrow)      s0[nb][1] = -1e30f;
                if (col > qrow + 8)      s0[nb][2] = -1e30f;
                if (col + 1 > qrow + 8)  s0[nb][3] = -1e30f;
                if (col > qrow + 16)     s1[nb][0] = -1e30f;
                if (col + 1 > qrow + 16) s1[nb][1] = -1e30f;
                if (col > qrow + 24)     s1[nb][2] = -1e30f;
                if (col + 1 > qrow + 24) s1[nb][3] = -1e30f;
            }
        }

        // ---- online softmax (4 rows per thread) ----
        float t0a = -1e30f, t0b = -1e30f, t1a = -1e30f, t1b = -1e30f;
        #pragma unroll
        for (int nb = 0; nb < 8; nb++) {
            t0a = fmaxf(t0a, fmaxf(s0[nb][0], s0[nb][1]));
            t0b = fmaxf(t0b, fmaxf(s0[nb][2], s0[nb][3]));
            t1a = fmaxf(t1a, fmaxf(s1[nb][0], s1[nb][1]));
            t1b = fmaxf(t1b, fmaxf(s1[nb][2], s1[nb][3]));
        }
        t0a = fmaxf(t0a, __shfl_xor_sync(0xFFFFFFFF, t0a, 1));
        t0a = fmaxf(t0a, __shfl_xor_sync(0xFFFFFFFF, t0a, 2));
        t0b = fmaxf(t0b, __shfl_xor_sync(0xFFFFFFFF, t0b, 1));
        t0b = fmaxf(t0b, __shfl_xor_sync(0xFFFFFFFF, t0b, 2));
        t1a = fmaxf(t1a, __shfl_xor_sync(0xFFFFFFFF, t1a, 1));
        t1a = fmaxf(t1a, __shfl_xor_sync(0xFFFFFFFF, t1a, 2));
        t1b = fmaxf(t1b, __shfl_xor_sync(0xFFFFFFFF, t1b, 1));
        t1b = fmaxf(t1b, __shfl_xor_sync(0xFFFFFFFF, t1b, 2));

        float n0a = fmaxf(m0a, t0a), n0b = fmaxf(m0b, t0b);
        float n1a = fmaxf(m1a, t1a), n1b = fmaxf(m1b, t1b);
        float a0a = __expf(m0a - n0a), a0b = __expf(m0b - n0b);
        float a1a = __expf(m1a - n1a), a1b = __expf(m1b - n1b);
        m0a = n0a; m0b = n0b; m1a = n1a; m1b = n1b;
        l0a *= a0a; l0b *= a0b; l1a *= a1a; l1b *= a1b;
        #pragma unroll
        for (int nb = 0; nb < 8; nb++) {
            o0[nb][0] *= a0a; o0[nb][1] *= a0a;
            o0[nb][2] *= a0b; o0[nb][3] *= a0b;
            o1[nb][0] *= a1a; o1[nb][1] *= a1a;
            o1[nb][2] *= a1b; o1[nb][3] *= a1b;
        }

        // ---- P = exp(S - m) -> warp-private smem (tf32) ----
        #pragma unroll
        for (int nb = 0; nb < 8; nb++) {
            int cc = 8 * nb + 2 * qj;
            float p0 = __expf(s0[nb][0] - m0a);
            float p1 = __expf(s0[nb][1] - m0a);
            float p2 = __expf(s0[nb][2] - m0b);
            float p3 = __expf(s0[nb][3] - m0b);
            l0a += p0 + p1; l0b += p2 + p3;
            *(float2*)&Pw[quad * PSP + cc] =
                make_float2(__uint_as_float(tf32r(p0)), __uint_as_float(tf32r(p1)));
            *(float2*)&Pw[(quad + 8) * PSP + cc] =
                make_float2(__uint_as_float(tf32r(p2)), __uint_as_float(tf32r(p3)));
            float p4 = __expf(s1[nb][0] - m1a);
            float p5 = __expf(s1[nb][1] - m1a);
            float p6 = __expf(s1[nb][2] - m1b);
            float p7 = __expf(s1[nb][3] - m1b);
            l1a += p4 + p5; l1b += p6 + p7;
            *(float2*)&Pw[(quad + 16) * PSP + cc] =
                make_float2(__uint_as_float(tf32r(p4)), __uint_as_float(tf32r(p5)));
            *(float2*)&Pw[(quad + 24) * PSP + cc] =
                make_float2(__uint_as_float(tf32r(p6)), __uint_as_float(tf32r(p7)));
        }
        __syncwarp();

        // ---- O += P V ----
        #pragma unroll
        for (int ks = 0; ks < 8; ks++) {
            const int kc = ks * 8 + qj;
            uint32_t a0[4], a1[4];
            a0[0] = __float_as_uint(Pw[quad * PSP + kc]);
            a0[1] = __float_as_uint(Pw[(quad + 8) * PSP + kc]);
            a0[2] = __float_as_uint(Pw[quad * PSP + kc + 4]);
            a0[3] = __float_as_uint(Pw[(quad + 8) * PSP + kc + 4]);
            a1[0] = __float_as_uint(Pw[(quad + 16) * PSP + kc]);
            a1[1] = __float_as_uint(Pw[(quad + 24) * PSP + kc]);
            a1[2] = __float_as_uint(Pw[(quad + 16) * PSP + kc + 4]);
            a1[3] = __float_as_uint(Pw[(quad + 24) * PSP + kc + 4]);
            #pragma unroll
            for (int nb = 0; nb < 8; nb++) {
                uint32_t b[2];
                b[0] = __float_as_uint(Vs[kc * VSP + 8 * nb + quad]);
                b[1] = __float_as_uint(Vs[(kc + 4) * VSP + 8 * nb + quad]);
                mma_tf32(o0[nb], a0, b);
                mma_tf32(o1[nb], a1, b);
            }
        }
        __syncthreads();
    }

    // ---- epilogue ----
    l0a += __shfl_xor_sync(0xFFFFFFFF, l0a, 1);
    l0a += __shfl_xor_sync(0xFFFFFFFF, l0a, 2);
    l0b += __shfl_xor_sync(0xFFFFFFFF, l0b, 1);
    l0b += __shfl_xor_sync(0xFFFFFFFF, l0b, 2);
    l1a += __shfl_xor_sync(0xFFFFFFFF, l1a, 1);
    l1a += __shfl_xor_sync(0xFFFFFFFF, l1a, 2);
    l1b += __shfl_xor_sync(0xFFFFFFFF, l1b, 1);
    l1b += __shfl_xor_sync(0xFFFFFFFF, l1b, 2);
    float i0a = 1.0f / l0a, i0b = 1.0f / l0b;
    float i1a = 1.0f / l1a, i1b = 1.0f / l1b;

    float* op = g_o + (size_t)qrow * DIM + h * HD;
    #pragma unroll
    for (int nb = 0; nb < 8; nb++) {
        int cc = 8 * nb + 2 * qj;
        *(float2*)(op + cc) = make_float2(
            __uint_as_float(tf32r(o0[nb][0] * i0a)),
            __uint_as_float(tf32r(o0[nb][1] * i0a)));
        *(float2*)(op + 8 * DIM + cc) = make_float2(
            __uint_as_float(tf32r(o0[nb][2] * i0b)),
            __uint_as_float(tf32r(o0[nb][3] * i0b)));
        *(float2*)(op + 16 * DIM + cc) = make_float2(
            __uint_as_float(tf32r(o1[nb][0] * i1a)),
            __uint_as_float(tf32r(o1[nb][1] * i1a)));
        *(float2*)(op + 24 * DIM + cc) = make_float2(
            __uint_as_float(tf32r(o1[nb][2] * i1b)),
            __uint_as_float(tf32r(o1[nb][3] * i1b)));
    }
}

// ---------------------------------------------------------------------------
// Launch
// ---------------------------------------------------------------------------
extern "C" void kernel_launch(void* const* d_in, const int* in_sizes, int n_in,
                              void* d_out, int out_size)
{
    const float* x  = (const float*)d_in[0];
    const float* Wq = (const float*)d_in[1];
    const float* Wk = (const float*)d_in[2];
    const float* Wv = (const float*)d_in[3];
    const float* Wo = (const float*)d_in[4];
    float* out = (float*)d_out;

    float *gq, *gk, *gv, *go, *gxr, *gwr;
    cudaGetSymbolAddress((void**)&gq, g_q);
    cudaGetSymbolAddress((void**)&gk, g_k);
    cudaGetSymbolAddress((void**)&gv, g_v);
    cudaGetSymbolAddress((void**)&go, g_o);
    cudaGetSymbolAddress((void**)&gxr, g_xr);
    cudaGetSymbolAddress((void**)&gwr, g_wr);

    cudaFuncSetAttribute(gemm_qkv,
                         cudaFuncAttributeMaxDynamicSharedMemorySize, GEMM_SMEM);
    cudaFuncSetAttribute(gemm_mma,
                         cudaFuncAttributeMaxDynamicSharedMemorySize, GEMM_SMEM);
    cudaFuncSetAttribute(flash_tc_kernel,
                         cudaFuncAttributeMaxDynamicSharedMemorySize, FA_SMEM);

    const int XW4 = S_LEN * DIM / 4;
    round_tf32_kernel<<<(XW4 + 255) / 256, 256>>>((const float4*)x, (float4*)gxr, XW4);
    round_w_kernel<<<4 * 1024, 256>>>((const float4*)Wq, (const float4*)Wk,
                                      (const float4*)Wv, (const float4*)Wo,
                                      (float4*)gwr);
    rope_table_kernel<<<(S_LEN * HALF_HD + 255) / 256, 256>>>();

    gemm_qkv<<<dim3(24, 32), 128, GEMM_SMEM>>>(gxr, gwr, gq, gk, gv);

    flash_tc_kernel<<<dim3(32, NH), 128, FA_SMEM>>>();

    gemm_mma<<<dim3(8, 32), 128, GEMM_SMEM>>>(go, gwr + 3 * DIM * DIM, out,
                                              S_LEN, DIM, DIM);
}

// round 14
// speedup vs baseline: 1.1524x; 1.0144x over previous
#include <cuda_runtime.h>
#include <cstdint>
#include <math.h>

#define S_LEN 4096
#define DIM 1024
#define NH 16
#define HD 64
#define HALF_HD 32

// ---------------------------------------------------------------------------
// Scratch (allocation-free)
// ---------------------------------------------------------------------------
__device__ float g_q[S_LEN * DIM];
__device__ float g_k[S_LEN * DIM];
__device__ float g_v[S_LEN * DIM];
__device__ float g_o[S_LEN * DIM];
__device__ float g_xr[S_LEN * DIM];
__device__ float g_wr[4 * DIM * DIM];
__device__ float g_cos[S_LEN * HALF_HD];
__device__ float g_sin[S_LEN * HALF_HD];

// ---------------------------------------------------------------------------
// Helpers
// ---------------------------------------------------------------------------
__device__ __forceinline__ uint32_t smem_u32(const void* p) {
    uint32_t a;
    asm("{ .reg .u64 t; cvta.to.shared.u64 t, %1; cvt.u32.u64 %0, t; }"
        : "=r"(a) : "l"(p));
    return a;
}

#define CP16(dst, src) \
    asm volatile("cp.async.cg.shared.global [%0], [%1], 16;" :: "r"(dst), "l"(src))
#define CP_COMMIT() asm volatile("cp.async.commit_group;" ::: "memory")
#define CP_WAIT(n)  asm volatile("cp.async.wait_group %0;" :: "n"(n) : "memory")

__device__ __forceinline__ void mma_tf32(float* c, const uint32_t* a, const uint32_t* b)
{
    asm volatile(
        "mma.sync.aligned.m16n8k8.row.col.f32.tf32.tf32.f32 "
        "{%0,%1,%2,%3}, {%4,%5,%6,%7}, {%8,%9}, {%0,%1,%2,%3};"
        : "+f"(c[0]), "+f"(c[1]), "+f"(c[2]), "+f"(c[3])
        : "r"(a[0]), "r"(a[1]), "r"(a[2]), "r"(a[3]), "r"(b[0]), "r"(b[1]));
}

__device__ __forceinline__ uint32_t tf32r(float x) {
    uint32_t u;
    asm("cvt.rna.tf32.f32 %0, %1;" : "=r"(u) : "f"(x));
    return u;
}

// ---------------------------------------------------------------------------
// GEMM config: C[M,N] = A[M,K] * B[N,K]^T, CTA tile 128x128, 128 threads,
// 4 warps (2x2), warp tile 64x64. BK=32, 2-stage cp.async, ONE sync/iter.
// ---------------------------------------------------------------------------
#define APITCH 36
#define STAGE_BYTES (128 * APITCH * 4)
#define GEMM_SMEM (4 * STAGE_BYTES)

#define GEMM_LOAD_TILE(s, kt, Abase, Bbase, K)                                 \
    do {                                                                       \
        const float* Ag = (Abase) + (size_t)bm * (K) + (kt) * 32;              \
        const float* Bg = (Bbase) + (size_t)bn * (K) + (kt) * 32;              \
        uint32_t adst = sbase + (s) * STAGE_BYTES;                             \
        uint32_t bdst = sbase + 2 * STAGE_BYTES + (s) * STAGE_BYTES;           \
        _Pragma("unroll")                                                      \
        for (int i = 0; i < 8; i++) {                                          \
            int idx = tid + i * 128;                                           \
            int row = idx >> 3, c4 = idx & 7;                                  \
            CP16(adst + row * 144 + c4 * 16, Ag + (size_t)row * (K) + c4 * 4); \
            CP16(bdst + row * 144 + c4 * 16, Bg + (size_t)row * (K) + c4 * 4); \
        }                                                                      \
    } while (0)

#define GEMM_MAINLOOP(Abase, Bbase, K)                                         \
    const int NK = (K) >> 5;                                                   \
    GEMM_LOAD_TILE(0, 0, Abase, Bbase, K);                                     \
    CP_COMMIT();                                                               \
    for (int kt = 0; kt < NK; kt++) {                                          \
        CP_WAIT(0);                                                            \
        __syncthreads();                                                       \
        if (kt + 1 < NK) {                                                     \
            GEMM_LOAD_TILE((kt + 1) & 1, kt + 1, Abase, Bbase, K);             \
            CP_COMMIT();                                                       \
        }                                                                      \
        const uint32_t* as = (const uint32_t*)(sh + (kt & 1) * STAGE_BYTES);   \
        const uint32_t* bs = (const uint32_t*)(sh + 2 * STAGE_BYTES + (kt & 1) * STAGE_BYTES); \
        _Pragma("unroll")                                                      \
        for (int ks = 0; ks < 4; ks++) {                                       \
            const int kc = ks * 8 + (lane & 3);                                \
            uint32_t af[4][4], bf[8][2];                                       \
            _Pragma("unroll")                                                  \
            for (int mi = 0; mi < 4; mi++) {                                   \
                int r = warp_m * 64 + mi * 16 + (lane >> 2);                   \
                af[mi][0] = as[r * APITCH + kc];                               \
                af[mi][1] = as[(r + 8) * APITCH + kc];                         \
                af[mi][2] = as[r * APITCH + kc + 4];                           \
                af[mi][3] = as[(r + 8) * APITCH + kc + 4];                     \
            }                                                                  \
            _Pragma("unroll")                                                  \
            for (int ni = 0; ni < 8; ni++) {                                   \
                int n = warp_n * 64 + ni * 8 + (lane >> 2);                    \
                bf[ni][0] = bs[n * APITCH + kc];                               \
                bf[ni][1] = bs[n * APITCH + kc + 4];                           \
            }                                                                  \
            _Pragma("unroll")                                                  \
            for (int mi = 0; mi < 4; mi++)                                     \
                _Pragma("unroll")                                              \
                for (int ni = 0; ni < 8; ni++)                                 \
                    mma_tf32(c[mi][ni], af[mi], bf[ni]);                       \
        }                                                                      \
    }

// ---------------------------------------------------------------------------
// Fused QKV GEMM: grid (24, 32): blockIdx.x>>3 selects {q,k,v}
// ---------------------------------------------------------------------------
__global__ __launch_bounds__(128) void gemm_qkv(
    const float* __restrict__ A, const float* __restrict__ Wbase,
    float* __restrict__ q, float* __restrict__ k, float* __restrict__ v)
{
    extern __shared__ char sh[];
    const uint32_t sbase = smem_u32(sh);
    const int tid  = threadIdx.x;
    const int lane = tid & 31;
    const int wid  = tid >> 5;
    const int warp_m = wid >> 1;
    const int warp_n = wid & 1;
    const int which = blockIdx.x >> 3;
    const int bm = blockIdx.y * 128;
    const int bn = (blockIdx.x & 7) * 128;
    const float* B = Wbase + (size_t)which * DIM * DIM;
    float* C = (which == 0) ? q : (which == 1) ? k : v;

    float c[4][8][4];
    #pragma unroll
    for (int i = 0; i < 4; i++)
        #pragma unroll
        for (int j = 0; j < 8; j++)
            #pragma unroll
            for (int kk = 0; kk < 4; kk++) c[i][j][kk] = 0.0f;

    GEMM_MAINLOOP(A, B, DIM);

    #pragma unroll
    for (int mi = 0; mi < 4; mi++) {
        int r0 = bm + warp_m * 64 + mi * 16 + (lane >> 2);
        #pragma unroll
        for (int ni = 0; ni < 8; ni++) {
            int col = bn + warp_n * 64 + ni * 8 + 2 * (lane & 3);
            float* cc = c[mi][ni];
            if (which < 2) {
                int p = (col & 63) >> 1;
                float c0 = g_cos[r0 * 32 + p],       s0 = g_sin[r0 * 32 + p];
                float c1 = g_cos[(r0 + 8) * 32 + p], s1 = g_sin[(r0 + 8) * 32 + p];
                float y0 = cc[0] * c0 - cc[1] * s0;
                float y1 = cc[1] * c0 + cc[0] * s0;
                float y2 = cc[2] * c1 - cc[3] * s1;
                float y3 = cc[3] * c1 + cc[2] * s1;
                *(float2*)(C + (size_t)r0 * DIM + col) = make_float2(
                    __uint_as_float(tf32r(y0)), __uint_as_float(tf32r(y1)));
                *(float2*)(C + (size_t)(r0 + 8) * DIM + col) = make_float2(
                    __uint_as_float(tf32r(y2)), __uint_as_float(tf32r(y3)));
            } else {
                *(float2*)(C + (size_t)r0 * DIM + col) = make_float2(
                    __uint_as_float(tf32r(cc[0])), __uint_as_float(tf32r(cc[1])));
                *(float2*)(C + (size_t)(r0 + 8) * DIM + col) = make_float2(
                    __uint_as_float(tf32r(cc[2])), __uint_as_float(tf32r(cc[3])));
            }
        }
    }
}

// ---------------------------------------------------------------------------
// Plain GEMM (Wo), fp32 output
// ---------------------------------------------------------------------------
__global__ __launch_bounds__(128) void gemm_mma(
    const float* __restrict__ A, const float* __restrict__ B,
    float* __restrict__ C, int M, int N, int K)
{
    extern __shared__ char sh[];
    const uint32_t sbase = smem_u32(sh);
    const int tid  = threadIdx.x;
    const int lane = tid & 31;
    const int wid  = tid >> 5;
    const int warp_m = wid >> 1;
    const int warp_n = wid & 1;
    const int bm = blockIdx.y * 128;
    const int bn = blockIdx.x * 128;

    float c[4][8][4];
    #pragma unroll
    for (int i = 0; i < 4; i++)
        #pragma unroll
        for (int j = 0; j < 8; j++)
            #pragma unroll
            for (int kk = 0; kk < 4; kk++) c[i][j][kk] = 0.0f;

    GEMM_MAINLOOP(A, B, K);

    #pragma unroll
    for (int mi = 0; mi < 4; mi++) {
        int r0 = bm + warp_m * 64 + mi * 16 + (lane >> 2);
        #pragma unroll
        for (int ni = 0; ni < 8; ni++) {
            int col = bn + warp_n * 64 + ni * 8 + 2 * (lane & 3);
            *(float2*)(C + (size_t)r0 * N + col) =
                make_float2(c[mi][ni][0], c[mi][ni][1]);
            *(float2*)(C + (size_t)(r0 + 8) * N + col) =
                make_float2(c[mi][ni][2], c[mi][ni][3]);
        }
    }
}

// ---------------------------------------------------------------------------
// Merged prep: round x, round 4 W matrices, build rope tables — one launch
// ---------------------------------------------------------------------------
#define PREP_NX (S_LEN * DIM / 4)
#define PREP_NW (DIM * DIM / 4)
#define PREP_NR (S_LEN * HALF_HD)
#define PREP_TOTAL (PREP_NX + 4 * PREP_NW + PREP_NR)

__global__ void prep_kernel(const float4* __restrict__ x,
                            const float4* __restrict__ w0,
                            const float4* __restrict__ w1,
                            const float4* __restrict__ w2,
                            const float4* __restrict__ w3,
                            float4* __restrict__ xr,
                            float4* __restrict__ wr)
{
    int i = blockIdx.x * blockDim.x + threadIdx.x;
    if (i < PREP_NX) {
        float4 v = x[i];
        xr[i] = make_float4(__uint_as_float(tf32r(v.x)), __uint_as_float(tf32r(v.y)),
                            __uint_as_float(tf32r(v.z)), __uint_as_float(tf32r(v.w)));
    } else if (i < PREP_NX + 4 * PREP_NW) {
        int j = i - PREP_NX;
        int which = j / PREP_NW;
        int off = j - which * PREP_NW;
        const float4* src = (which == 0) ? w0 : (which == 1) ? w1
                          : (which == 2) ? w2 : w3;
        float4 v = src[off];
        wr[j] = make_float4(__uint_as_float(tf32r(v.x)), __uint_as_float(tf32r(v.y)),
                            __uint_as_float(tf32r(v.z)), __uint_as_float(tf32r(v.w)));
    } else {
        int idx = i - PREP_NX - 4 * PREP_NW;
        if (idx < PREP_NR) {
            int s = idx / HALF_HD;
            int p = idx % HALF_HD;
            double inv = exp((double)p * -0.28782313662425572);
            double ang = (double)s * inv;
            double t = floor(ang * 0.15915494309189535);
            float r = (float)(ang - t * 6.283185307179586);
            float sn, cs;
            sincosf(r, &sn, &cs);
            g_cos[idx] = cs;
            g_sin[idx] = sn;
        }
    }
}

// ---------------------------------------------------------------------------
// Tensor-core causal flash attention. 128 threads, 4 warps x 32 q-rows.
// Base-2 softmax (log2e folded into Q scale). ONE sync per key tile.
// ---------------------------------------------------------------------------
#define KSP 68
#define VSP 72
#define PSP 68
#define FA_KS_BYTES (64 * KSP * 4)
#define FA_VS_BYTES (64 * VSP * 4)
#define FA_VS_OFF   (2 * FA_KS_BYTES)
#define FA_P_OFF    (2 * FA_KS_BYTES + 2 * FA_VS_BYTES)
#define FA_SMEM     (FA_P_OFF + 128 * PSP * 4)

__global__ __launch_bounds__(128, 2) void flash_tc_kernel()
{
    extern __shared__ char sh[];
    float* shf = (float*)sh;
    const uint32_t sbase = smem_u32(sh);
    const int tid  = threadIdx.x;
    const int lane = tid & 31;
    const int w    = tid >> 5;
    const int quad = lane >> 2;
    const int qj   = lane & 3;
    const int qt   = 31 - blockIdx.x;
    const int h    = blockIdx.y;

    const int qrow = qt * 128 + 32 * w + quad;

    // Q scale folds 1/sqrt(64) and log2(e): scores emerge in base-2 units
    const float QSC = 0.125f * 1.4426950408889634f;

    uint32_t qa0[8][4], qa1[8][4];
    {
        const float* qp = g_q + (size_t)qrow * DIM + h * HD;
        #pragma unroll
        for (int ks = 0; ks < 8; ks++) {
            int kc = ks * 8 + qj;
            qa0[ks][0] = __float_as_uint(qp[kc] * QSC);
            qa0[ks][1] = __float_as_uint(qp[8 * DIM + kc] * QSC);
            qa0[ks][2] = __float_as_uint(qp[kc + 4] * QSC);
            qa0[ks][3] = __float_as_uint(qp[8 * DIM + kc + 4] * QSC);
            qa1[ks][0] = __float_as_uint(qp[16 * DIM + kc] * QSC);
            qa1[ks][1] = __float_as_uint(qp[24 * DIM + kc] * QSC);
            qa1[ks][2] = __float_as_uint(qp[16 * DIM + kc + 4] * QSC);
            qa1[ks][3] = __float_as_uint(qp[24 * DIM + kc + 4] * QSC);
        }
    }

    float o0[8][4], o1[8][4];
    #pragma unroll
    for (int nb = 0; nb < 8; nb++)
        #pragma unroll
        for (int i = 0; i < 4; i++) { o0[nb][i] = 0.0f; o1[nb][i] = 0.0f; }

    float m0a = -1e30f, m0b = -1e30f, m1a = -1e30f, m1b = -1e30f;
    float l0a = 0.0f, l0b = 0.0f, l1a = 0.0f, l1b = 0.0f;

    const int nkt = 2 * qt + 2;

    #define FA_LOAD(kt, b) do {                                               \
        const float* Kg = g_k + (size_t)(kt) * 64 * DIM + h * HD;             \
        const float* Vg = g_v + (size_t)(kt) * 64 * DIM + h * HD;             \
        uint32_t kd = sbase + (b) * FA_KS_BYTES;                              \
        uint32_t vd = sbase + FA_VS_OFF + (b) * FA_VS_BYTES;                  \
        _Pragma("unroll")                                                     \
        for (int i = 0; i < 8; i++) {                                         \
            int idx = tid + i * 128;                                          \
            int r = idx >> 4, c4 = idx & 15;                                  \
            CP16(kd + r * (KSP * 4) + c4 * 16, Kg + (size_t)r * DIM + c4 * 4);\
            CP16(vd + r * (VSP * 4) + c4 * 16, Vg + (size_t)r * DIM + c4 * 4);\
        }                                                                     \
    } while (0)

    FA_LOAD(0, 0);
    CP_COMMIT();

    float* Pw = shf + FA_P_OFF / 4 + 32 * w * PSP;

    for (int kt = 0; kt < nkt; kt++) {
        CP_WAIT(0);
        __syncthreads();
        if (kt + 1 < nkt) {
            FA_LOAD(kt + 1, (kt + 1) & 1);
            CP_COMMIT();
        }

        const float* Ks = shf + (kt & 1) * (FA_KS_BYTES / 4);
        const float* Vs = shf + FA_VS_OFF / 4 + (kt & 1) * (FA_VS_BYTES / 4);

        // ---- S2 = (Q * 0.125*log2e) K^T  (base-2 logits) ----
        float s0[8][4], s1[8][4];
        #pragma unroll
        for (int nb = 0; nb < 8; nb++)
            #pragma unroll
            for (int i = 0; i < 4; i++) { s0[nb][i] = 0.0f; s1[nb][i] = 0.0f; }

        #pragma unroll
        for (int ks = 0; ks < 8; ks++) {
            const int kc = ks * 8 + qj;
            #pragma unroll
            for (int nb = 0; nb < 8; nb++) {
                uint32_t b[2];
                b[0] = __float_as_uint(Ks[(8 * nb + quad) * KSP + kc]);
                b[1] = __float_as_uint(Ks[(8 * nb + quad) * KSP + kc + 4]);
                mma_tf32(s0[nb], qa0[ks], b);
                mma_tf32(s1[nb], qa1[ks], b);
            }
        }

        // ---- causal mask ----
        if (kt >= 2 * qt) {
            #pragma unroll
            for (int nb = 0; nb < 8; nb++) {
                int col = kt * 64 + 8 * nb + 2 * qj;
                if (col > qrow)          s0[nb][0] = -1e30f;
                if (col + 1 > qrow)      s0[nb][1] = -1e30f;
                if (col > qrow + 8)      s0[nb][2] = -1e30f;
                if (col + 1 > qrow + 8)  s0[nb][3] = -1e30f;
                if (col > qrow + 16)     s1[nb][0] = -1e30f;
                if (col + 1 > qrow + 16) s1[nb][1] = -1e30f;
                if (col > qrow + 24)     s1[nb][2] = -1e30f;
                if (col + 1 > qrow + 24) s1[nb][3] = -1e30f;
            }
        }

        // ---- online softmax (base 2) ----
        float t0a = -1e30f, t0b = -1e30f, t1a = -1e30f, t1b = -1e30f;
        #pragma unroll
        for (int nb = 0; nb < 8; nb++) {
            t0a = fmaxf(t0a, fmaxf(s0[nb][0], s0[nb][1]));
            t0b = fmaxf(t0b, fmaxf(s0[nb][2], s0[nb][3]));
            t1a = fmaxf(t1a, fmaxf(s1[nb][0], s1[nb][1]));
            t1b = fmaxf(t1b, fmaxf(s1[nb][2], s1[nb][3]));
        }
        t0a = fmaxf(t0a, __shfl_xor_sync(0xFFFFFFFF, t0a, 1));
        t0a = fmaxf(t0a, __shfl_xor_sync(0xFFFFFFFF, t0a, 2));
        t0b = fmaxf(t0b, __shfl_xor_sync(0xFFFFFFFF, t0b, 1));
        t0b = fmaxf(t0b, __shfl_xor_sync(0xFFFFFFFF, t0b, 2));
        t1a = fmaxf(t1a, __shfl_xor_sync(0xFFFFFFFF, t1a, 1));
        t1a = fmaxf(t1a, __shfl_xor_sync(0xFFFFFFFF, t1a, 2));
        t1b = fmaxf(t1b, __shfl_xor_sync(0xFFFFFFFF, t1b, 1));
        t1b = fmaxf(t1b, __shfl_xor_sync(0xFFFFFFFF, t1b, 2));

        float n0a = fmaxf(m0a, t0a), n0b = fmaxf(m0b, t0b);
        float n1a = fmaxf(m1a, t1a), n1b = fmaxf(m1b, t1b);
        float a0a = exp2f(m0a - n0a), a0b = exp2f(m0b - n0b);
        float a1a = exp2f(m1a - n1a), a1b = exp2f(m1b - n1b);
        m0a = n0a; m0b = n0b; m1a = n1a; m1b = n1b;
        l0a *= a0a; l0b *= a0b; l1a *= a1a; l1b *= a1b;
        #pragma unroll
        for (int nb = 0; nb < 8; nb++) {
            o0[nb][0] *= a0a; o0[nb][1] *= a0a;
            o0[nb][2] *= a0b; o0[nb][3] *= a0b;
            o1[nb][0] *= a1a; o1[nb][1] *= a1a;
            o1[nb][2] *= a1b; o1[nb][3] *= a1b;
        }

        // ---- P = 2^(S2 - m2) -> warp-private smem (tf32) ----
        #pragma unroll
        for (int nb = 0; nb < 8; nb++) {
            int cc = 8 * nb + 2 * qj;
            float p0 = exp2f(s0[nb][0] - m0a);
            float p1 = exp2f(s0[nb][1] - m0a);
            float p2 = exp2f(s0[nb][2] - m0b);
            float p3 = exp2f(s0[nb][3] - m0b);
            l0a += p0 + p1; l0b += p2 + p3;
            *(float2*)&Pw[quad * PSP + cc] =
                make_float2(__uint_as_float(tf32r(p0)), __uint_as_float(tf32r(p1)));
            *(float2*)&Pw[(quad + 8) * PSP + cc] =
                make_float2(__uint_as_float(tf32r(p2)), __uint_as_float(tf32r(p3)));
            float p4 = exp2f(s1[nb][0] - m1a);
            float p5 = exp2f(s1[nb][1] - m1a);
            float p6 = exp2f(s1[nb][2] - m1b);
            float p7 = exp2f(s1[nb][3] - m1b);
            l1a += p4 + p5; l1b += p6 + p7;
            *(float2*)&Pw[(quad + 16) * PSP + cc] =
                make_float2(__uint_as_float(tf32r(p4)), __uint_as_float(tf32r(p5)));
            *(float2*)&Pw[(quad + 24) * PSP + cc] =
                make_float2(__uint_as_float(tf32r(p6)), __uint_as_float(tf32r(p7)));
        }
        __syncwarp();

        // ---- O += P V ----
        #pragma unroll
        for (int ks = 0; ks < 8; ks++) {
            const int kc = ks * 8 + qj;
            uint32_t a0[4], a1[4];
            a0[0] = __float_as_uint(Pw[quad * PSP + kc]);
            a0[1] = __float_as_uint(Pw[(quad + 8) * PSP + kc]);
            a0[2] = __float_as_uint(Pw[quad * PSP + kc + 4]);
            a0[3] = __float_as_uint(Pw[(quad + 8) * PSP + kc + 4]);
            a1[0] = __float_as_uint(Pw[(quad + 16) * PSP + kc]);
            a1[1] = __float_as_uint(Pw[(quad + 24) * PSP + kc]);
            a1[2] = __float_as_uint(Pw[(quad + 16) * PSP + kc + 4]);
            a1[3] = __float_as_uint(Pw[(quad + 24) * PSP + kc + 4]);
            #pragma unroll
            for (int nb = 0; nb < 8; nb++) {
                uint32_t b[2];
                b[0] = __float_as_uint(Vs[kc * VSP + 8 * nb + quad]);
                b[1] = __float_as_uint(Vs[(kc + 4) * VSP + 8 * nb + quad]);
                mma_tf32(o0[nb], a0, b);
                mma_tf32(o1[nb], a1, b);
            }
        }
    }

    // ---- epilogue ----
    l0a += __shfl_xor_sync(0xFFFFFFFF, l0a, 1);
    l0a += __shfl_xor_sync(0xFFFFFFFF, l0a, 2);
    l0b += __shfl_xor_sync(0xFFFFFFFF, l0b, 1);
    l0b += __shfl_xor_sync(0xFFFFFFFF, l0b, 2);
    l1a += __shfl_xor_sync(0xFFFFFFFF, l1a, 1);
    l1a += __shfl_xor_sync(0xFFFFFFFF, l1a, 2);
    l1b += __shfl_xor_sync(0xFFFFFFFF, l1b, 1);
    l1b += __shfl_xor_sync(0xFFFFFFFF, l1b, 2);
    float i0a = 1.0f / l0a, i0b = 1.0f / l0b;
    float i1a = 1.0f / l1a, i1b = 1.0f / l1b;

    float* op = g_o + (size_t)qrow * DIM + h * HD;
    #pragma unroll
    for (int nb = 0; nb < 8; nb++) {
        int cc = 8 * nb + 2 * qj;
        *(float2*)(op + cc) = make_float2(
            __uint_as_float(tf32r(o0[nb][0] * i0a)),
            __uint_as_float(tf32r(o0[nb][1] * i0a)));
        *(float2*)(op + 8 * DIM + cc) = make_float2(
            __uint_as_float(tf32r(o0[nb][2] * i0b)),
            __uint_as_float(tf32r(o0[nb][3] * i0b)));
        *(float2*)(op + 16 * DIM + cc) = make_float2(
            __uint_as_float(tf32r(o1[nb][0] * i1a)),
            __uint_as_float(tf32r(o1[nb][1] * i1a)));
        *(float2*)(op + 24 * DIM + cc) = make_float2(
            __uint_as_float(tf32r(o1[nb][2] * i1b)),
            __uint_as_float(tf32r(o1[nb][3] * i1b)));
    }
}

// ---------------------------------------------------------------------------
// Launch
// ---------------------------------------------------------------------------
extern "C" void kernel_launch(void* const* d_in, const int* in_sizes, int n_in,
                              void* d_out, int out_size)
{
    const float* x  = (const float*)d_in[0];
    const float* Wq = (const float*)d_in[1];
    const float* Wk = (const float*)d_in[2];
    const float* Wv = (const float*)d_in[3];
    const float* Wo = (const float*)d_in[4];
    float* out = (float*)d_out;

    float *gq, *gk, *gv, *go, *gxr, *gwr;
    cudaGetSymbolAddress((void**)&gq, g_q);
    cudaGetSymbolAddress((void**)&gk, g_k);
    cudaGetSymbolAddress((void**)&gv, g_v);
    cudaGetSymbolAddress((void**)&go, g_o);
    cudaGetSymbolAddress((void**)&gxr, g_xr);
    cudaGetSymbolAddress((void**)&gwr, g_wr);

    cudaFuncSetAttribute(gemm_qkv,
                         cudaFuncAttributeMaxDynamicSharedMemorySize, GEMM_SMEM);
    cudaFuncSetAttribute(gemm_mma,
                         cudaFuncAttributeMaxDynamicSharedMemorySize, GEMM_SMEM);
    cudaFuncSetAttribute(flash_tc_kernel,
                         cudaFuncAttributeMaxDynamicSharedMemorySize, FA_SMEM);

    prep_kernel<<<(PREP_TOTAL + 255) / 256, 256>>>(
        (const float4*)x, (const float4*)Wq, (const float4*)Wk,
        (const float4*)Wv, (const float4*)Wo, (float4*)gxr, (float4*)gwr);

    gemm_qkv<<<dim3(24, 32), 128, GEMM_SMEM>>>(gxr, gwr, gq, gk, gv);

    flash_tc_kernel<<<dim3(32, NH), 128, FA_SMEM>>>();

    gemm_mma<<<dim3(8, 32), 128, GEMM_SMEM>>>(go, gwr + 3 * DIM * DIM, out,
                                              S_LEN, DIM, DIM);
}